// round 9
// baseline (speedup 1.0000x reference)
#include <cuda_runtime.h>
#include <cuda_fp16.h>

// FastFood layer, D=1024, R=4, M=16384 rows. ONE WARP PER ROW-PAIR. Zero shuffles.
// Lane value = f32x2 pair (rowA[i], rowB[i]); butterflies via add.rn.f32x2 / fma.rn.f32x2.
// smem image element = half2 of the pair (4B word); layouts A/B as before:
//   A: idx = k*32 + l      B: idx = l*32 + k
// Image rows: 36 words (144B, 16B-aligned). slot(i) = (i>>5)*36 + (i&31) (word index).
// Column sweeps = STS.32/LDS.32 conflict-free (banks 4k+lane distinct); row sweeps = uint4.
// PG table entry (4B): (slot<<16) | half_bits(G), 4 entries per LDG.128; shared by both rows.

#define FF_D 1024
#define FF_R 4
#define WPB 8
#define THREADS (WPB * 32)
#define RS 36   // 4B words per image row

typedef unsigned long long u64;

__device__ unsigned int g_bpack[FF_R * 32];   // bit k = signbit(B[r][k*32+l])
__device__ int4         g_pg4[FF_R * 256];    // [r][q*32+l] = entries for j = l*32+4q+{0..3}
__device__ float        g_spre[FF_R * FF_D];  // S / 32, natural order

__global__ void prep_kernel(const float* __restrict__ B, const float* __restrict__ G,
                            const float* __restrict__ S, const int* __restrict__ P) {
    int t = blockIdx.x * blockDim.x + threadIdx.x;
    int stride = gridDim.x * blockDim.x;
    if (t < FF_R * 32) {
        int r = t >> 5, l = t & 31;
        unsigned int m = 0;
        #pragma unroll
        for (int k = 0; k < 32; k++)
            m |= (__float_as_uint(B[r * FF_D + k * 32 + l]) >> 31) << k;
        g_bpack[t] = m;
    }
    for (int i = t; i < FF_R * 256; i += stride) {
        int r = i >> 8, rem = i & 255;
        int q = rem >> 5, l = rem & 31;
        int j = r * FF_D + l * 32 + 4 * q;
        unsigned int e[4];
        #pragma unroll
        for (int u = 0; u < 4; u++) {
            int p = P[j + u];
            unsigned int slot = (unsigned int)((p >> 5) * RS + (p & 31));   // word index
            unsigned short gh = __half_as_ushort(__float2half_rn(G[j + u]));
            e[u] = (slot << 16) | (unsigned int)gh;
        }
        g_pg4[i] = make_int4((int)e[0], (int)e[1], (int)e[2], (int)e[3]);
    }
    for (int i = t; i < FF_R * FF_D; i += stride)
        g_spre[i] = S[i] * 0.03125f;             // 1/sqrt(1024)
}

// ---- f32x2 helpers ----
__device__ __forceinline__ u64 pk(float a, float b) {
    u64 u; asm("mov.b64 %0, {%1,%2};" : "=l"(u) : "f"(a), "f"(b)); return u;
}
__device__ __forceinline__ float2 up(u64 u) {
    float2 r; asm("mov.b64 {%0,%1}, %2;" : "=f"(r.x), "=f"(r.y) : "l"(u)); return r;
}
__device__ __forceinline__ u64 addx2(u64 a, u64 b) {
    u64 r; asm("add.rn.f32x2 %0, %1, %2;" : "=l"(r) : "l"(a), "l"(b)); return r;
}
__device__ __forceinline__ u64 subx2(u64 a, u64 b) {        // a - b (exact: fma with -1)
    u64 r;
    asm("fma.rn.f32x2 %0, %1, %2, %3;" : "=l"(r)
        : "l"(b), "l"(0xBF800000BF800000ULL), "l"(a));
    return r;
}
__device__ __forceinline__ unsigned int h2pack(u64 v) {      // f32x2 -> half2 bits
    float2 f = up(v);
    __half2 h = __floats2half2_rn(f.x, f.y);
    return *reinterpret_cast<unsigned int*>(&h);
}
__device__ __forceinline__ float2 h2unpack(unsigned int w) { // half2 bits -> float2
    __half2 h = *reinterpret_cast<__half2*>(&w);
    return __half22float2(h);
}

__device__ __forceinline__ void fwht2(u64 v[32]) {
    // H32 over the 5 register-index bits, both rows at once
    #pragma unroll
    for (int m = 1; m <= 16; m <<= 1) {
        #pragma unroll
        for (int k = 0; k < 32; k++) {
            if ((k & m) == 0) {
                u64 a = v[k], b = v[k | m];
                v[k]     = addx2(a, b);
                v[k | m] = subx2(a, b);
            }
        }
    }
}

__global__ __launch_bounds__(THREADS, 2)
void fastfood_kernel(const float* __restrict__ x,
                     float* __restrict__ out, int M)
{
    __shared__ unsigned int sc[WPB][32 * RS];    // 4608 B per warp-pair image
    const int warp = threadIdx.x >> 5;
    const int lane = threadIdx.x & 31;
    const int pr   = blockIdx.x * WPB + warp;    // row-pair index
    const int row0 = 2 * pr;
    if (row0 >= M) return;
    const bool has1 = (row0 + 1) < M;
    unsigned int* smw = sc[warp];
    uint4* myrow = reinterpret_cast<uint4*>(smw + lane * RS);   // 144B rows: 16B aligned

    const float* xr0 = x + (size_t)row0 * FF_D;
    const float* xr1 = has1 ? xr0 + FF_D : xr0;

    #pragma unroll 1
    for (int r = 0; r < FF_R; r++) {
        // ---- v = (x0,x1) * B[r] (sign-bit xor), layout A ----
        const unsigned int bp = g_bpack[r * 32 + lane];
        u64 v[32];
        #pragma unroll
        for (int k = 0; k < 32; k++) {
            unsigned int msk = (bp << (31 - k)) & 0x80000000u;
            float lo = __uint_as_float(__float_as_uint(__ldg(&xr0[k * 32 + lane])) ^ msk);
            float hi = __uint_as_float(__float_as_uint(__ldg(&xr1[k * 32 + lane])) ^ msk);
            v[k] = pk(lo, hi);
        }

        // ---- FWHT #1: high bits (A) ----
        fwht2(v);
        // transpose A -> B: STS.32 column writes (banks 4k+lane: CF), uint4 row reads
        #pragma unroll
        for (int k = 0; k < 32; k++) smw[k * RS + lane] = h2pack(v[k]);
        __syncwarp();
        #pragma unroll
        for (int q = 0; q < 8; q++) {
            uint4 d = myrow[q];
            float2 a = h2unpack(d.x), b = h2unpack(d.y);
            float2 c = h2unpack(d.z), e = h2unpack(d.w);
            v[4*q+0] = pk(a.x, a.y); v[4*q+1] = pk(b.x, b.y);
            v[4*q+2] = pk(c.x, c.y); v[4*q+3] = pk(e.x, e.y);
        }
        // ---- FWHT #1: low bits (B) -> h1 ----
        fwht2(v);

        // ---- gather image: own-row uint4 writes (no sync), random LDS.32 reads ----
        #pragma unroll
        for (int q = 0; q < 8; q++)
            myrow[q] = make_uint4(h2pack(v[4*q+0]), h2pack(v[4*q+1]),
                                  h2pack(v[4*q+2]), h2pack(v[4*q+3]));
        __syncwarp();
        const int4* PG = g_pg4 + r * 256;
        #pragma unroll
        for (int q = 0; q < 8; q++) {
            int4 pg = __ldg(&PG[q * 32 + lane]);               // 4 table entries
            unsigned int ee[4] = {(unsigned int)pg.x, (unsigned int)pg.y,
                                  (unsigned int)pg.z, (unsigned int)pg.w};
            #pragma unroll
            for (int u = 0; u < 4; u++) {
                float2 t = h2unpack(smw[ee[u] >> 16]);          // both rows, permuted
                float g = __half2float(__ushort_as_half((unsigned short)(ee[u] & 0xffffu)));
                v[4*q+u] = pk(t.x * g, t.y * g);
            }
        }
        __syncwarp();                                           // all gathers done before overwrite

        // ---- FWHT #2: low bits (B) ----
        fwht2(v);
        // transpose B -> A: own-row uint4 writes, STS->LDS.32 column reads
        #pragma unroll
        for (int q = 0; q < 8; q++)
            myrow[q] = make_uint4(h2pack(v[4*q+0]), h2pack(v[4*q+1]),
                                  h2pack(v[4*q+2]), h2pack(v[4*q+3]));
        __syncwarp();
        #pragma unroll
        for (int k = 0; k < 32; k++) {
            float2 t = h2unpack(smw[k * RS + lane]);
            v[k] = pk(t.x, t.y);
        }
        // ---- FWHT #2: high bits (A) ----
        fwht2(v);

        // ---- scale (prescaled fp32 S, shared by both rows) + coalesced stores ----
        const float* Sp = g_spre + r * FF_D;
        float* o0 = out + (size_t)row0 * (FF_R * FF_D) + r * FF_D;
        float* o1 = o0 + (FF_R * FF_D);
        #pragma unroll
        for (int k = 0; k < 32; k++) {
            int j = k * 32 + lane;
            float s = __ldg(&Sp[j]);
            float2 t = up(v[k]);
            o0[j] = t.x * s;
            if (has1) o1[j] = t.y * s;
        }
    }
}

extern "C" void kernel_launch(void* const* d_in, const int* in_sizes, int n_in,
                              void* d_out, int out_size) {
    const float* x = (const float*)d_in[0];   // (4,512,8,1024) fp32
    const float* B = (const float*)d_in[1];   // (4,1024) fp32
    const float* G = (const float*)d_in[2];   // (4,1024) fp32
    const float* S = (const float*)d_in[3];   // (4,1024) fp32
    const int*   P = (const int*)  d_in[4];   // (4,1024) int32
    float* out = (float*)d_out;

    const int M = in_sizes[0] / FF_D;         // 16384 rows
    prep_kernel<<<32, 256>>>(B, G, S, P);
    const int pairs = (M + 1) / 2;
    const int blocks = (pairs + WPB - 1) / WPB;
    fastfood_kernel<<<blocks, THREADS>>>(x, out, M);
}

// round 10
// speedup vs baseline: 1.4761x; 1.4761x over previous
#include <cuda_runtime.h>
#include <cuda_fp16.h>

// FastFood layer, D=1024, R=4, M=16384 rows. One warp per row. Zero shuffles.
// R8 structure (fp16 smem image, packed PG table) + f32x2 register-pair butterflies:
// va[p] (u64) = fp32 pair (elem (2p)*32+l, elem (2p+1)*32+l). 4 of 5 butterfly stages
// are pair-uniform (add/fma.rn.f32x2); the within-pair stage is fma(v,{1,-1},swap(v)).
//
// Layouts: A: idx = k*32 + l   B: idx = l*32 + k  (k = reg, l = lane)
// Image: 32 rows x 36 halves (72B rows). slot(i) = (i>>5)*36 + (i&31).
// PG entry (4B) = (slot<<16) | half_bits(G). S stored as half2 reg-pairs, prescaled /32.

#define FF_D 1024
#define FF_R 4
#define WPB 8
#define THREADS (WPB * 32)
#define RS 36   // halves per image row

typedef unsigned long long u64;

__device__ unsigned int g_bpack[FF_R * 32];   // bit k = signbit(B[r][k*32+l])
__device__ int4         g_pg4[FF_R * 256];    // [r][q*32+l]: entries for j = l*32+4q+{0..3}
__device__ unsigned int g_sh2[FF_R * 512];    // [r][p*32+l] = half2(S'[2p*32+l], S'[(2p+1)*32+l])

__global__ void prep_kernel(const float* __restrict__ B, const float* __restrict__ G,
                            const float* __restrict__ S, const int* __restrict__ P) {
    int t = blockIdx.x * blockDim.x + threadIdx.x;
    int stride = gridDim.x * blockDim.x;
    if (t < FF_R * 32) {
        int r = t >> 5, l = t & 31;
        unsigned int m = 0;
        #pragma unroll
        for (int k = 0; k < 32; k++)
            m |= (__float_as_uint(B[r * FF_D + k * 32 + l]) >> 31) << k;
        g_bpack[t] = m;
    }
    for (int i = t; i < FF_R * 256; i += stride) {
        int r = i >> 8, rem = i & 255;
        int q = rem >> 5, l = rem & 31;
        int j = r * FF_D + l * 32 + 4 * q;
        unsigned int e[4];
        #pragma unroll
        for (int u = 0; u < 4; u++) {
            int p = P[j + u];
            unsigned int slot = (unsigned int)((p >> 5) * RS + (p & 31));
            unsigned short gh = __half_as_ushort(__float2half_rn(G[j + u]));
            e[u] = (slot << 16) | (unsigned int)gh;
        }
        g_pg4[i] = make_int4((int)e[0], (int)e[1], (int)e[2], (int)e[3]);
    }
    for (int i = t; i < FF_R * 512; i += stride) {
        int r = i >> 9, rem = i & 511;
        int p = rem >> 5, l = rem & 31;
        float s0 = S[r * FF_D + (2 * p)     * 32 + l] * 0.03125f;
        float s1 = S[r * FF_D + (2 * p + 1) * 32 + l] * 0.03125f;
        __half2 h = __floats2half2_rn(s0, s1);
        g_sh2[i] = *reinterpret_cast<unsigned int*>(&h);
    }
}

// ---- f32x2 helpers ----
__device__ __forceinline__ u64 pk(float a, float b) {
    u64 u; asm("mov.b64 %0, {%1,%2};" : "=l"(u) : "f"(a), "f"(b)); return u;
}
__device__ __forceinline__ float2 up(u64 u) {
    float2 r; asm("mov.b64 {%0,%1}, %2;" : "=f"(r.x), "=f"(r.y) : "l"(u)); return r;
}
__device__ __forceinline__ u64 swp(u64 v) {   // swap halves (register renaming)
    u64 r;
    asm("{\n\t.reg .b32 a,b;\n\tmov.b64 {a,b}, %1;\n\tmov.b64 %0, {b,a};\n\t}"
        : "=l"(r) : "l"(v));
    return r;
}
__device__ __forceinline__ u64 addx2(u64 a, u64 b) {
    u64 r; asm("add.rn.f32x2 %0, %1, %2;" : "=l"(r) : "l"(a), "l"(b)); return r;
}
__device__ __forceinline__ u64 fmax2(u64 a, u64 b, u64 c) {   // a*b + c
    u64 r; asm("fma.rn.f32x2 %0, %1, %2, %3;" : "=l"(r) : "l"(a), "l"(b), "l"(c)); return r;
}
__device__ __forceinline__ u64 mulx2(u64 a, u64 b) {
    u64 r; asm("mul.rn.f32x2 %0, %1, %2;" : "=l"(r) : "l"(a), "l"(b)); return r;
}
#define C_P1M1 0xBF8000003F800000ULL   // {+1.0, -1.0}
#define C_M1M1 0xBF800000BF800000ULL   // {-1.0, -1.0}

__device__ __forceinline__ unsigned int h2pack(u64 v) {      // f32x2 -> half2 bits
    float2 f = up(v);
    __half2 h = __floats2half2_rn(f.x, f.y);
    return *reinterpret_cast<unsigned int*>(&h);
}
__device__ __forceinline__ float2 h2unpack(unsigned int w) {
    __half2 h = *reinterpret_cast<__half2*>(&w);
    return __half22float2(h);
}

// H32 over the 5 register-index bits on 16 packed pairs.
__device__ __forceinline__ void fwht2x(u64 va[16]) {
    // within-pair stage (reg bit 0): (a,b) -> (a+b, a-b)
    #pragma unroll
    for (int p = 0; p < 16; p++)
        va[p] = fmax2(va[p], C_P1M1, swp(va[p]));
    // pair-uniform stages (reg bits 1..4)
    #pragma unroll
    for (int m = 1; m <= 8; m <<= 1) {
        #pragma unroll
        for (int p = 0; p < 16; p++) {
            if ((p & m) == 0) {
                u64 a = va[p], b = va[p | m];
                va[p]     = addx2(a, b);
                va[p | m] = fmax2(b, C_M1M1, a);   // a - b
            }
        }
    }
}

__global__ __launch_bounds__(THREADS, 4)
void fastfood_kernel(const float* __restrict__ x,
                     float* __restrict__ out, int M)
{
    __shared__ __half sc[WPB][32 * RS];
    const int warp = threadIdx.x >> 5;
    const int lane = threadIdx.x & 31;
    const int row  = blockIdx.x * WPB + warp;
    if (row >= M) return;
    __half* smh = sc[warp];
    uint2* myrow = reinterpret_cast<uint2*>(smh + lane * RS);   // 72B rows: 8B aligned
    const float* xr = x + (size_t)row * FF_D;

    #pragma unroll 1
    for (int r = 0; r < FF_R; r++) {
        // ---- v = x * B[r] (sign-bit xor), layout A, packed pairs ----
        const unsigned int bp = g_bpack[r * 32 + lane];
        u64 va[16];
        #pragma unroll
        for (int p = 0; p < 16; p++) {
            unsigned int m0 = (bp << (31 - 2 * p))     & 0x80000000u;
            unsigned int m1 = (bp << (31 - 2 * p - 1)) & 0x80000000u;
            float lo = __uint_as_float(__float_as_uint(__ldg(&xr[(2 * p)     * 32 + lane])) ^ m0);
            float hi = __uint_as_float(__float_as_uint(__ldg(&xr[(2 * p + 1) * 32 + lane])) ^ m1);
            va[p] = pk(lo, hi);
        }

        // ---- FWHT #1: high bits (A) ----
        fwht2x(va);
        // transpose A -> B: scalar fp16 column writes, half4 row reads
        #pragma unroll
        for (int p = 0; p < 16; p++) {
            float2 f = up(va[p]);
            smh[(2 * p)     * RS + lane] = __float2half_rn(f.x);
            smh[(2 * p + 1) * RS + lane] = __float2half_rn(f.y);
        }
        __syncwarp();
        #pragma unroll
        for (int q = 0; q < 8; q++) {
            uint2 d = myrow[q];
            float2 a = h2unpack(d.x), b = h2unpack(d.y);
            va[2 * q]     = pk(a.x, a.y);
            va[2 * q + 1] = pk(b.x, b.y);
        }
        // ---- FWHT #1: low bits (B) -> h1 ----
        fwht2x(va);

        // ---- gather image: own-row writes, random permuted reads ----
        #pragma unroll
        for (int q = 0; q < 8; q++)
            myrow[q] = make_uint2(h2pack(va[2 * q]), h2pack(va[2 * q + 1]));
        __syncwarp();
        const int4* PG = g_pg4 + r * 256;
        #pragma unroll
        for (int q = 0; q < 8; q++) {
            int4 pg = __ldg(&PG[q * 32 + lane]);
            unsigned int e0 = (unsigned int)pg.x, e1 = (unsigned int)pg.y;
            unsigned int e2 = (unsigned int)pg.z, e3 = (unsigned int)pg.w;
            float t0 = __half2float(smh[e0 >> 16]);
            float t1 = __half2float(smh[e1 >> 16]);
            float t2 = __half2float(smh[e2 >> 16]);
            float t3 = __half2float(smh[e3 >> 16]);
            float g0 = __half2float(__ushort_as_half((unsigned short)(e0 & 0xffffu)));
            float g1 = __half2float(__ushort_as_half((unsigned short)(e1 & 0xffffu)));
            float g2 = __half2float(__ushort_as_half((unsigned short)(e2 & 0xffffu)));
            float g3 = __half2float(__ushort_as_half((unsigned short)(e3 & 0xffffu)));
            va[2 * q]     = mulx2(pk(t0, t1), pk(g0, g1));
            va[2 * q + 1] = mulx2(pk(t2, t3), pk(g2, g3));
        }
        __syncwarp();                                   // gathers done before overwrite

        // ---- FWHT #2: low bits (B) ----
        fwht2x(va);
        // transpose B -> A: own-row writes, scalar fp16 column reads
        #pragma unroll
        for (int q = 0; q < 8; q++)
            myrow[q] = make_uint2(h2pack(va[2 * q]), h2pack(va[2 * q + 1]));
        __syncwarp();
        #pragma unroll
        for (int p = 0; p < 16; p++) {
            float f0 = __half2float(smh[(2 * p)     * RS + lane]);
            float f1 = __half2float(smh[(2 * p + 1) * RS + lane]);
            va[p] = pk(f0, f1);
        }
        // ---- FWHT #2: high bits (A) ----
        fwht2x(va);

        // ---- scale (half2-paired prescaled S) + coalesced store ----
        const unsigned int* Sh = g_sh2 + r * 512;
        float* o = out + (size_t)row * (FF_R * FF_D) + r * FF_D;
        #pragma unroll
        for (int p = 0; p < 16; p++) {
            float2 s = h2unpack(__ldg(&Sh[p * 32 + lane]));
            float2 t = up(mulx2(va[p], pk(s.x, s.y)));
            o[(2 * p)     * 32 + lane] = t.x;
            o[(2 * p + 1) * 32 + lane] = t.y;
        }
    }
}

extern "C" void kernel_launch(void* const* d_in, const int* in_sizes, int n_in,
                              void* d_out, int out_size) {
    const float* x = (const float*)d_in[0];   // (4,512,8,1024) fp32
    const float* B = (const float*)d_in[1];   // (4,1024) fp32
    const float* G = (const float*)d_in[2];   // (4,1024) fp32
    const float* S = (const float*)d_in[3];   // (4,1024) fp32
    const int*   P = (const int*)  d_in[4];   // (4,1024) int32
    float* out = (float*)d_out;

    const int M = in_sizes[0] / FF_D;         // 16384 rows
    prep_kernel<<<32, 256>>>(B, G, S, P);
    const int blocks = (M + WPB - 1) / WPB;
    fastfood_kernel<<<blocks, THREADS>>>(x, out, M);
}